// round 12
// baseline (speedup 1.0000x reference)
#include <cuda_runtime.h>
#include <cuda_bf16.h>
#include <cstdint>

#define NLINES 12288       // 24 planes * 512 lines
#define LW 512
#define KS 121
#define MT 256             // output rows per CTA (2 warps-strips x 8 warps)
#define KT 384             // K span: 256 + 120 pad -> 24 chunks of 16
#define PB 784             // B row pitch bytes (384 bf16 + 16B pad; 196 words % 32 = 4)

// dynamic smem layout
#define SM_BH 0            // B_hi [64 n][384 k] bf16, pitch PB: 50176 B
#define SM_BL 50176        // B_lo: 50176 B
#define SM_TBH 100352      // u32[176] hi pair table T[i] = (w[i-16], w[i-15])
#define SM_TBL 101056      // u32[176] lo table
#define SM_SRED 101760     // float[128]
#define SM_TOTAL 102272    // x2 CTAs = 204.5 KB / SM

__device__ float g_tmp[NLINES * LW];

static __device__ __forceinline__ void mma_bf16(float* c, uint32_t a0, uint32_t a1,
                                                uint32_t a2, uint32_t a3,
                                                uint32_t b0, uint32_t b1) {
    asm volatile(
        "mma.sync.aligned.m16n8k16.row.col.f32.bf16.bf16.f32 "
        "{%0,%1,%2,%3}, {%4,%5,%6,%7}, {%8,%9}, {%0,%1,%2,%3};"
        : "+f"(c[0]), "+f"(c[1]), "+f"(c[2]), "+f"(c[3])
        : "r"(a0), "r"(a1), "r"(a2), "r"(a3), "r"(b0), "r"(b1));
}

static __device__ __forceinline__ uint32_t pack_bf2(float lo, float hi) {
    __nv_bfloat162 h;
    h.x = __float2bfloat16(lo);
    h.y = __float2bfloat16(hi);
    return *(uint32_t*)&h;
}

// ---------------------------------------------------------------------------
// One separable-blur pass as banded GEMM (mma.sync bf16, 3-term hi/lo split,
// fp32 accum).  Each warp owns TWO 16-row m-strips sharing B fragments:
// strip1's Toeplitz A-fragments are the pair table shifted by -16.
// Output written plane-transposed; two passes compose to correct layout.
// ---------------------------------------------------------------------------
__global__ __launch_bounds__(256, 2)
void blur_pass(const float* __restrict__ x, float* __restrict__ outp,
               const float* __restrict__ sigma, int first) {
    extern __shared__ char smem[];
    int tid = threadIdx.x;
    int ib = blockIdx.x;             // 0..1: 256-row output block along the line
    int L0 = blockIdx.y * 64;        // first line of the 64-line tile
    int Mb = ib * MT;

    const float* in = first ? x : (const float*)g_tmp;
    float* out = first ? (float*)g_tmp : outp;

    // ---- B build: 64 lines x 192 k-pairs; thread = (line-group, lane64) ----
    {
        int lane64 = tid & 63;
        int lg0 = (tid >> 6) * 16;
        #pragma unroll 1
        for (int ln = 0; ln < 16; ln++) {
            int n = lg0 + ln;
            const float* ip = in + (long)(L0 + n) * LW;
            char* bh = smem + SM_BH + n * PB;
            char* bl = smem + SM_BL + n * PB;
            #pragma unroll
            for (int pp = 0; pp < 3; pp++) {
                int pair = lane64 + 64 * pp;          // 0..191
                int gx0 = min(max(Mb - 60 + 2 * pair, 0), LW - 1);
                int gx1 = min(max(Mb - 60 + 2 * pair + 1, 0), LW - 1);
                float v0 = ip[gx0], v1 = ip[gx1];
                float h0 = __bfloat162float(__float2bfloat16(v0));
                float h1 = __bfloat162float(__float2bfloat16(v1));
                *(uint32_t*)(bh + pair * 4) = pack_bf2(v0, v1);
                *(uint32_t*)(bl + pair * 4) = pack_bf2(v0 - h0, v1 - h1);
            }
        }
    }

    // ---- weights + pair tables ----
    {
        float* sred = (float*)(smem + SM_SRED);
        float e = 0.0f;
        if (tid < 128) {
            float s = sigma[0] * 8.0f + 16.0f;
            float d = (float)(tid - 60);
            e = (tid < KS) ? expf(-(d * d) / (2.0f * s * s)) : 0.0f;
            sred[tid] = e;
        }
        __syncthreads();
        float* wf = (float*)(smem + SM_SRED);
        if (tid < 32) {
            float s4 = sred[tid] + sred[tid + 32] + sred[tid + 64] + sred[tid + 96];
            #pragma unroll
            for (int off = 16; off > 0; off >>= 1)
                s4 += __shfl_xor_sync(0xffffffffu, s4, off);
            if (tid == 0) sred[0] = s4;
        }
        __syncthreads();
        float sum = wf[0];
        __syncthreads();
        if (tid < 128) wf[tid] = e / sum;            // wf[121..127] = 0
        __syncthreads();
        if (tid < 176) {
            int i = tid - 16;
            float w0 = ((unsigned)i < 128u) ? wf[i] : 0.0f;
            float w1 = ((unsigned)(i + 1) < 128u) ? wf[i + 1] : 0.0f;
            float h0 = __bfloat162float(__float2bfloat16(w0));
            float h1 = __bfloat162float(__float2bfloat16(w1));
            ((uint32_t*)(smem + SM_TBH))[tid] = pack_bf2(w0, w1);
            ((uint32_t*)(smem + SM_TBL))[tid] = pack_bf2(w0 - h0, w1 - h1);
        }
    }
    __syncthreads();

    // ---- mainloop: warp = strips m0 = 32*wid and m0+16; 10 k-chunks ----
    int wid = tid >> 5, lane = tid & 31;
    int g = lane >> 2, t = lane & 3;
    int mwb = wid * 32;

    float c0[8][4], c1[8][4];
    #pragma unroll
    for (int j = 0; j < 8; j++)
        #pragma unroll
        for (int r = 0; r < 4; r++) { c0[j][r] = 0.0f; c1[j][r] = 0.0f; }

    const uint32_t* tbh = (const uint32_t*)(smem + SM_TBH);
    const uint32_t* tbl = (const uint32_t*)(smem + SM_TBL);
    const char* bhp = smem + SM_BH + g * PB + (mwb + 2 * t) * 2;
    const char* blp = smem + SM_BL + g * PB + (mwb + 2 * t) * 2;
    int di0 = 2 * t - g + 16;

    #pragma unroll 1
    for (int u = 0; u < 10; u++) {
        int idx = di0 + 16 * u;
        int s0act = (u < 9), s1act = (u > 0);

        uint32_t ah0 = 0, ah1 = 0, ah2 = 0, al0 = 0, al1 = 0, al2 = 0;
        uint32_t sh0 = 0, sh1 = 0, sh2 = 0, sl0 = 0, sl1 = 0, sl2 = 0;
        if (s0act) {
            ah0 = tbh[idx]; ah1 = tbh[idx - 8]; ah2 = tbh[idx + 8];
            al0 = tbl[idx]; al1 = tbl[idx - 8]; al2 = tbl[idx + 8];
        }
        if (s1act) {
            sh0 = tbh[idx - 16]; sh1 = tbh[idx - 24]; sh2 = tbh[idx - 8];
            sl0 = tbl[idx - 16]; sl1 = tbl[idx - 24]; sl2 = tbl[idx - 8];
        }

        uint32_t b[8][2];
        const char* bp = bhp + u * 32;
        #pragma unroll
        for (int j = 0; j < 8; j++) {
            b[j][0] = *(const uint32_t*)(bp + j * 8 * PB);
            b[j][1] = *(const uint32_t*)(bp + j * 8 * PB + 16);
        }
        if (s0act) {
            #pragma unroll
            for (int j = 0; j < 8; j++)
                mma_bf16(c0[j], ah0, ah1, ah2, ah0, b[j][0], b[j][1]);   // Ah*Bh
            #pragma unroll
            for (int j = 0; j < 8; j++)
                mma_bf16(c0[j], al0, al1, al2, al0, b[j][0], b[j][1]);   // Al*Bh
        }
        if (s1act) {
            #pragma unroll
            for (int j = 0; j < 8; j++)
                mma_bf16(c1[j], sh0, sh1, sh2, sh0, b[j][0], b[j][1]);
            #pragma unroll
            for (int j = 0; j < 8; j++)
                mma_bf16(c1[j], sl0, sl1, sl2, sl0, b[j][0], b[j][1]);
        }

        const char* lp = blp + u * 32;
        #pragma unroll
        for (int j = 0; j < 8; j++) {
            b[j][0] = *(const uint32_t*)(lp + j * 8 * PB);
            b[j][1] = *(const uint32_t*)(lp + j * 8 * PB + 16);
        }
        if (s0act) {
            #pragma unroll
            for (int j = 0; j < 8; j++)
                mma_bf16(c0[j], ah0, ah1, ah2, ah0, b[j][0], b[j][1]);   // Ah*Bl
        }
        if (s1act) {
            #pragma unroll
            for (int j = 0; j < 8; j++)
                mma_bf16(c1[j], sh0, sh1, sh2, sh0, b[j][0], b[j][1]);
        }
    }

    // ---- epilogue: plane-transposed store, strips at rows +0 / +16 ----
    {
        int p = L0 >> 9;
        int lp0 = L0 & 511;
        long row = (long)p * 512 + Mb + mwb + g;
        float* o0 = out + row * 512 + lp0;
        #pragma unroll
        for (int j = 0; j < 8; j++) {
            int n = 8 * j + 2 * t;
            *(float2*)(o0 + n) = make_float2(c0[j][0], c0[j][1]);
            *(float2*)(o0 + 8 * 512 + n) = make_float2(c0[j][2], c0[j][3]);
        }
        float* o1 = o0 + 16 * 512;
        #pragma unroll
        for (int j = 0; j < 8; j++) {
            int n = 8 * j + 2 * t;
            *(float2*)(o1 + n) = make_float2(c1[j][0], c1[j][1]);
            *(float2*)(o1 + 8 * 512 + n) = make_float2(c1[j][2], c1[j][3]);
        }
    }
}

// ---------------------------------------------------------------------------
extern "C" void kernel_launch(void* const* d_in, const int* in_sizes, int n_in,
                              void* d_out, int out_size) {
    const float* x     = (const float*)d_in[0];
    const float* sigma = (const float*)d_in[1];
    float* out = (float*)d_out;

    cudaFuncSetAttribute(blur_pass, cudaFuncAttributeMaxDynamicSharedMemorySize,
                         SM_TOTAL);

    dim3 grid(LW / MT, NLINES / 64);    // 2 x 192 = 384 CTAs
    blur_pass<<<grid, 256, SM_TOTAL>>>(x, out, sigma, 1);   // x -> g_tmp (T)
    blur_pass<<<grid, 256, SM_TOTAL>>>(x, out, sigma, 0);   // g_tmp -> out (T back)
}

// round 13
// speedup vs baseline: 1.2576x; 1.2576x over previous
#include <cuda_runtime.h>
#include <cuda_bf16.h>
#include <cstdint>

#define NLINES 12288       // 24 planes * 512 lines
#define LW 512
#define KS 121
#define PB 528             // B row pitch in bytes (256 bf16 + 16B pad)

// dynamic smem layout
#define SM_BH 0            // B_hi [64 n][256 k] bf16, pitch PB: 33792 B
#define SM_BL 33792        // B_lo: 33792 B
#define SM_TBH 67584       // u32[176] hi pair table T[i] = (w[i-16], w[i-15])
#define SM_TBL 68288       // u32[176] lo table
#define SM_SRED 68992      // float[128]
#define SM_TOTAL 69504     // 3 CTAs/SM = 208.5 KB

__device__ float g_tmp[NLINES * LW];

static __device__ __forceinline__ uint32_t s2u(const void* p) {
    uint32_t a;
    asm("{ .reg .u64 t; cvta.to.shared.u64 t, %1; cvt.u32.u64 %0, t; }" : "=r"(a) : "l"(p));
    return a;
}

static __device__ __forceinline__ void mma_bf16(float* c, uint32_t a0, uint32_t a1,
                                                uint32_t a2, uint32_t a3,
                                                uint32_t b0, uint32_t b1) {
    asm volatile(
        "mma.sync.aligned.m16n8k16.row.col.f32.bf16.bf16.f32 "
        "{%0,%1,%2,%3}, {%4,%5,%6,%7}, {%8,%9}, {%0,%1,%2,%3};"
        : "+f"(c[0]), "+f"(c[1]), "+f"(c[2]), "+f"(c[3])
        : "r"(a0), "r"(a1), "r"(a2), "r"(a3), "r"(b0), "r"(b1));
}

// one ldmatrix.x4: loads B fragments for j-tiles (2i, 2i+1), both k-halves
static __device__ __forceinline__ void ldm4(uint32_t& r0, uint32_t& r1,
                                            uint32_t& r2, uint32_t& r3, uint32_t adr) {
    asm volatile("ldmatrix.sync.aligned.m8n8.x4.shared.b16 {%0,%1,%2,%3}, [%4];"
                 : "=r"(r0), "=r"(r1), "=r"(r2), "=r"(r3) : "r"(adr));
}

static __device__ __forceinline__ uint32_t pack_bf2(float lo, float hi) {
    __nv_bfloat162 h;
    h.x = __float2bfloat16(lo);
    h.y = __float2bfloat16(hi);
    return *(uint32_t*)&h;
}

// ---------------------------------------------------------------------------
// One separable-blur pass as banded GEMM on tensor cores (mma.sync bf16,
// 3-term hi/lo error split, fp32 accum).  A[m,k] = w[k-m] Toeplitz band is
// generated from a 176-entry pair table (never materialized).  B fragments
// loaded with ldmatrix.x4 (4 fragments / instruction).  Output written
// plane-transposed; two passes compose to the correct layout.
// ---------------------------------------------------------------------------
__global__ __launch_bounds__(256)
void blur_pass(const float* __restrict__ x, float* __restrict__ outp,
               const float* __restrict__ sigma, int first) {
    extern __shared__ char smem[];
    uint32_t sbu = s2u(smem);
    int tid = threadIdx.x;
    int ib = blockIdx.x;             // 0..3: output block along the line
    int L0 = blockIdx.y * 64;        // first line of the 64-line tile

    const float* in = first ? x : (const float*)g_tmp;
    float* out = first ? (float*)g_tmp : outp;

    // ---- B build: thread = (k-pair k2 = tid&127, line-half = tid>>7) ----
    {
        int k2 = tid & 127, half = tid >> 7;
        int gx0 = min(max(ib * 128 - 60 + 2 * k2, 0), LW - 1);
        int gx1 = min(max(ib * 128 - 60 + 2 * k2 + 1, 0), LW - 1);
        const float* ip0 = in + (long)(L0 + half * 32) * LW + gx0;
        const float* ip1 = in + (long)(L0 + half * 32) * LW + gx1;
        char* bh = smem + SM_BH + half * 32 * PB + k2 * 4;
        char* bl = smem + SM_BL + half * 32 * PB + k2 * 4;
        #pragma unroll 4
        for (int n = 0; n < 32; n++) {
            float v0 = ip0[(long)n * LW];
            float v1 = ip1[(long)n * LW];
            float h0 = __bfloat162float(__float2bfloat16(v0));
            float h1 = __bfloat162float(__float2bfloat16(v1));
            *(uint32_t*)(bh + n * PB) = pack_bf2(v0, v1);
            *(uint32_t*)(bl + n * PB) = pack_bf2(v0 - h0, v1 - h1);
        }
    }

    // ---- weights + pair tables ----
    {
        float* sred = (float*)(smem + SM_SRED);
        float e = 0.0f;
        if (tid < 128) {
            float s = sigma[0] * 8.0f + 16.0f;
            float d = (float)(tid - 60);
            e = (tid < KS) ? expf(-(d * d) / (2.0f * s * s)) : 0.0f;
            sred[tid] = e;
        }
        __syncthreads();
        float* wf = (float*)(smem + SM_SRED);
        if (tid < 32) {
            float s4 = sred[tid] + sred[tid + 32] + sred[tid + 64] + sred[tid + 96];
            #pragma unroll
            for (int off = 16; off > 0; off >>= 1)
                s4 += __shfl_xor_sync(0xffffffffu, s4, off);
            if (tid == 0) sred[0] = s4;
        }
        __syncthreads();
        float sum = wf[0];
        __syncthreads();
        if (tid < 128) wf[tid] = e / sum;            // wf[121..127] = 0
        __syncthreads();
        if (tid < 176) {
            int i = tid - 16;
            float w0 = ((unsigned)i < 128u) ? wf[i] : 0.0f;
            float w1 = ((unsigned)(i + 1) < 128u) ? wf[i + 1] : 0.0f;
            float h0 = __bfloat162float(__float2bfloat16(w0));
            float h1 = __bfloat162float(__float2bfloat16(w1));
            ((uint32_t*)(smem + SM_TBH))[tid] = pack_bf2(w0, w1);
            ((uint32_t*)(smem + SM_TBL))[tid] = pack_bf2(w0 - h0, w1 - h1);
        }
    }
    __syncthreads();

    // ---- mainloop: warp = 16-row m-strip; 9 active k-chunks (band) ----
    int wid = tid >> 5, lane = tid & 31;
    int g = lane >> 2, t = lane & 3;
    int m0 = wid * 16;

    float c[8][4];
    #pragma unroll
    for (int j = 0; j < 8; j++)
        #pragma unroll
        for (int r = 0; r < 4; r++) c[j][r] = 0.0f;

    const uint32_t* tbh = (const uint32_t*)(smem + SM_TBH);
    const uint32_t* tbl = (const uint32_t*)(smem + SM_TBL);

    // ldmatrix lane address: matrix mi = lane>>3 -> (j_sub = mi>>1, khalf = mi&1),
    // row rr = lane&7.  addr(i,u) = A0h + i*16*PB + u*32.
    int mi = lane >> 3, rr = lane & 7;
    uint32_t A0h = sbu + SM_BH + (uint32_t)((8 * (mi >> 1) + rr) * PB)
                 + (uint32_t)(16 * (mi & 1)) + (uint32_t)(m0 * 2);
    uint32_t A0l = A0h + (SM_BL - SM_BH);
    int di0 = 2 * t - g + 16;

    #pragma unroll 1
    for (int u = 0; u < 9; u++) {
        int idx = di0 + 16 * u;
        uint32_t ah0 = tbh[idx], ah1 = tbh[idx - 8], ah2 = tbh[idx + 8];
        uint32_t al0 = tbl[idx], al1 = tbl[idx - 8], al2 = tbl[idx + 8];

        uint32_t b[8][2];
        uint32_t ah = A0h + u * 32;
        ldm4(b[0][0], b[0][1], b[1][0], b[1][1], ah);
        ldm4(b[2][0], b[2][1], b[3][0], b[3][1], ah + 16 * PB);
        ldm4(b[4][0], b[4][1], b[5][0], b[5][1], ah + 32 * PB);
        ldm4(b[6][0], b[6][1], b[7][0], b[7][1], ah + 48 * PB);

        #pragma unroll
        for (int j = 0; j < 8; j++)
            mma_bf16(c[j], ah0, ah1, ah2, ah0, b[j][0], b[j][1]);   // Ah*Bh
        #pragma unroll
        for (int j = 0; j < 8; j++)
            mma_bf16(c[j], al0, al1, al2, al0, b[j][0], b[j][1]);   // Al*Bh

        uint32_t al = A0l + u * 32;
        ldm4(b[0][0], b[0][1], b[1][0], b[1][1], al);
        ldm4(b[2][0], b[2][1], b[3][0], b[3][1], al + 16 * PB);
        ldm4(b[4][0], b[4][1], b[5][0], b[5][1], al + 32 * PB);
        ldm4(b[6][0], b[6][1], b[7][0], b[7][1], al + 48 * PB);

        #pragma unroll
        for (int j = 0; j < 8; j++)
            mma_bf16(c[j], ah0, ah1, ah2, ah0, b[j][0], b[j][1]);   // Ah*Bl
    }

    // ---- epilogue: D[m][n] -> plane-transposed store ----
    {
        int p = L0 >> 9;                // plane
        int lp0 = L0 & 511;             // line within plane
        long row = (long)(p * 512 + ib * 128 + m0 + g);
        float* o0 = out + row * 512 + lp0;
        float* o1 = o0 + 8 * 512;       // row +8
        #pragma unroll
        for (int j = 0; j < 8; j++) {
            int n = 8 * j + 2 * t;
            *(float2*)(o0 + n) = make_float2(c[j][0], c[j][1]);
            *(float2*)(o1 + n) = make_float2(c[j][2], c[j][3]);
        }
    }
}

// ---------------------------------------------------------------------------
extern "C" void kernel_launch(void* const* d_in, const int* in_sizes, int n_in,
                              void* d_out, int out_size) {
    const float* x     = (const float*)d_in[0];
    const float* sigma = (const float*)d_in[1];
    float* out = (float*)d_out;

    cudaFuncSetAttribute(blur_pass, cudaFuncAttributeMaxDynamicSharedMemorySize,
                         SM_TOTAL);

    dim3 grid(LW / 128, NLINES / 64);   // 4 x 192 = 768 CTAs
    blur_pass<<<grid, 256, SM_TOTAL>>>(x, out, sigma, 1);   // x -> g_tmp (T)
    blur_pass<<<grid, 256, SM_TOTAL>>>(x, out, sigma, 0);   // g_tmp -> out (T back)
}